// round 5
// baseline (speedup 1.0000x reference)
#include <cuda_runtime.h>
#include <cuda_bf16.h>
#include <math.h>
#include <stdint.h>

#define D_MODEL 1024
#define HEADS 16
#define HEAD_DIM 64
#define BATCH 4
#define SEQ 2048
#define MTOT (BATCH * SEQ) /* 8192 */
#define WSZ (D_MODEL * D_MODEL)

typedef __nv_bfloat16 bf16;

// ---- scratch (static __device__; allocation APIs forbidden) ----
__device__ bf16 g_xh[(size_t)MTOT * D_MODEL];
__device__ bf16 g_xl[(size_t)MTOT * D_MODEL];
__device__ bf16 g_qkvh[(size_t)3 * MTOT * D_MODEL];
__device__ bf16 g_qkvl[(size_t)3 * MTOT * D_MODEL];
__device__ bf16 g_mh[(size_t)MTOT * D_MODEL];
__device__ bf16 g_ml[(size_t)MTOT * D_MODEL];
__device__ bf16 g_wh[(size_t)3 * WSZ];
__device__ bf16 g_wl[(size_t)3 * WSZ];

// ============================ PTX helpers ============================
__device__ __forceinline__ uint32_t smem_u32(const void* p) {
    uint32_t a;
    asm("{ .reg .u64 t; cvta.to.shared.u64 t, %1; cvt.u32.u64 %0, t; }"
        : "=r"(a) : "l"(p));
    return a;
}
__device__ __forceinline__ void cp16(uint32_t s, const void* g) {
    asm volatile("cp.async.cg.shared.global [%0], [%1], 16;" :: "r"(s), "l"(g) : "memory");
}
__device__ __forceinline__ void cp_commit() {
    asm volatile("cp.async.commit_group;" ::: "memory");
}
template <int N> __device__ __forceinline__ void cp_wait() {
    asm volatile("cp.async.wait_group %0;" :: "n"(N) : "memory");
}
__device__ __forceinline__ void ldsm4(uint32_t* r, uint32_t addr) {
    asm volatile("ldmatrix.sync.aligned.m8n8.x4.shared.b16 {%0,%1,%2,%3}, [%4];"
                 : "=r"(r[0]), "=r"(r[1]), "=r"(r[2]), "=r"(r[3]) : "r"(addr));
}
__device__ __forceinline__ void ldsm4t(uint32_t* r, uint32_t addr) {
    asm volatile("ldmatrix.sync.aligned.m8n8.x4.trans.shared.b16 {%0,%1,%2,%3}, [%4];"
                 : "=r"(r[0]), "=r"(r[1]), "=r"(r[2]), "=r"(r[3]) : "r"(addr));
}
__device__ __forceinline__ void mma16816(float* c, const uint32_t* a,
                                         uint32_t b0, uint32_t b1) {
    asm volatile(
        "mma.sync.aligned.m16n8k16.row.col.f32.bf16.bf16.f32 "
        "{%0,%1,%2,%3},{%4,%5,%6,%7},{%8,%9},{%0,%1,%2,%3};"
        : "+f"(c[0]), "+f"(c[1]), "+f"(c[2]), "+f"(c[3])
        : "r"(a[0]), "r"(a[1]), "r"(a[2]), "r"(a[3]), "r"(b0), "r"(b1));
}
__device__ __forceinline__ uint32_t bf2(bf16 a, bf16 b) {
    __nv_bfloat162 t; t.x = a; t.y = b;
    return *(uint32_t*)&t;
}

// ============================ mma.sync GEMM ============================
// C[M,1024] = A[M,1024] @ W[1024,1024]. A bf16 hi/lo, W pre-transposed
// Wt[n][k] bf16 hi/lo. 3-term split. 128x128 tile, BK=32, 8 warps (4x2).
// Output: either fp32 Cf, or bf16 hi/lo split (scale applied for z==0).
#define BK 32
#define NCHUNK (D_MODEL / BK) /* 32 */
#define ROW_B 80
#define TILE_B (128 * ROW_B)
#define STAGE_B (4 * TILE_B)
#define GEMM_SMEM (2 * STAGE_B) /* 81920 */

__global__ __launch_bounds__(256, 2) void gemm_mma(
    const bf16* __restrict__ Ah, const bf16* __restrict__ Al,
    const bf16* __restrict__ BhAll, const bf16* __restrict__ BlAll,
    float* __restrict__ Cf, bf16* __restrict__ ChAll, bf16* __restrict__ ClAll,
    float scale0)
{
    extern __shared__ char smem[];
    const uint32_t sb = smem_u32(smem);
    const int tid = threadIdx.x;
    const int wid = tid >> 5, lane = tid & 31;
    const int wm = wid & 3, wn = wid >> 2;
    const int rowBase = blockIdx.y * 128;
    const int colBase = blockIdx.x * 128;

    const bf16* Bh = BhAll + (size_t)blockIdx.z * WSZ;
    const bf16* Bl = BlAll + (size_t)blockIdx.z * WSZ;

    const bf16* src[4] = {
        Ah + (size_t)rowBase * D_MODEL, Al + (size_t)rowBase * D_MODEL,
        Bh + (size_t)colBase * D_MODEL, Bl + (size_t)colBase * D_MODEL};

    float acc[2][8][4];
#pragma unroll
    for (int mi = 0; mi < 2; mi++)
#pragma unroll
        for (int ni = 0; ni < 8; ni++)
#pragma unroll
            for (int j = 0; j < 4; j++) acc[mi][ni][j] = 0.f;

    auto load_chunk = [&](int c, int s) {
        const uint32_t tb = sb + s * STAGE_B;
        const int kofs = c * BK;
#pragma unroll
        for (int t = 0; t < 4; t++) {
#pragma unroll
            for (int i = 0; i < 2; i++) {
                int f = i * 256 + tid;
                int row = f >> 2, cc = f & 3;
                cp16(tb + t * TILE_B + row * ROW_B + cc * 16,
                     src[t] + (size_t)row * D_MODEL + kofs + cc * 8);
            }
        }
    };

    const uint32_t lrow = lane & 15, lcol = lane >> 4;
    const int pa[3] = {0, 0, 1};
    const int pb[3] = {2, 3, 2};

    load_chunk(0, 0);
    cp_commit();

    for (int c = 0; c < NCHUNK; c++) {
        if (c + 1 < NCHUNK) {
            load_chunk(c + 1, (c + 1) & 1);
            cp_commit();
            cp_wait<1>();
        } else {
            cp_wait<0>();
        }
        __syncthreads();

        const uint32_t tb = sb + (c & 1) * STAGE_B;
#pragma unroll
        for (int p = 0; p < 3; p++) {
            const uint32_t aT = tb + pa[p] * TILE_B;
            const uint32_t bT = tb + pb[p] * TILE_B;
#pragma unroll
            for (int k16 = 0; k16 < 2; k16++) {
                const uint32_t kb = k16 * 32;
                uint32_t a[2][4];
#pragma unroll
                for (int mi = 0; mi < 2; mi++)
                    ldsm4(a[mi], aT + (wm * 32 + mi * 16 + lrow) * ROW_B + kb + lcol * 16);
                uint32_t bfr[4][4];
#pragma unroll
                for (int nb = 0; nb < 4; nb++)
                    ldsm4(bfr[nb], bT + (wn * 64 + nb * 16 + lrow) * ROW_B + kb + lcol * 16);
#pragma unroll
                for (int mi = 0; mi < 2; mi++)
#pragma unroll
                    for (int ni = 0; ni < 8; ni++) {
                        int nb = ni >> 1, hl = ni & 1;
                        mma16816(acc[mi][ni], a[mi], bfr[nb][hl], bfr[nb][hl + 2]);
                    }
            }
        }
        __syncthreads();
    }

    // Epilogue
    const int g = lane >> 2, t4 = lane & 3;
    if (ChAll) {
        bf16* Ch = ChAll + (size_t)blockIdx.z * MTOT * D_MODEL;
        bf16* Cl = ClAll + (size_t)blockIdx.z * MTOT * D_MODEL;
        const float sc = (blockIdx.z == 0) ? scale0 : 1.0f;
#pragma unroll
        for (int mi = 0; mi < 2; mi++)
#pragma unroll
            for (int ni = 0; ni < 8; ni++) {
                int r = rowBase + wm * 32 + mi * 16 + g;
                int col = colBase + wn * 64 + ni * 8 + t4 * 2;
#pragma unroll
                for (int half = 0; half < 2; half++) {
                    float v0 = acc[mi][ni][2 * half] * sc;
                    float v1 = acc[mi][ni][2 * half + 1] * sc;
                    bf16 h0 = __float2bfloat16(v0);
                    bf16 h1 = __float2bfloat16(v1);
                    bf16 l0 = __float2bfloat16(v0 - __bfloat162float(h0));
                    bf16 l1 = __float2bfloat16(v1 - __bfloat162float(h1));
                    size_t o = (size_t)(r + 8 * half) * D_MODEL + col;
                    *(uint32_t*)&Ch[o] = bf2(h0, h1);
                    *(uint32_t*)&Cl[o] = bf2(l0, l1);
                }
            }
    } else {
#pragma unroll
        for (int mi = 0; mi < 2; mi++)
#pragma unroll
            for (int ni = 0; ni < 8; ni++) {
                int r = rowBase + wm * 32 + mi * 16 + g;
                int col = colBase + wn * 64 + ni * 8 + t4 * 2;
                *(float2*)&Cf[(size_t)r * D_MODEL + col] =
                    make_float2(acc[mi][ni][0], acc[mi][ni][1]);
                *(float2*)&Cf[(size_t)(r + 8) * D_MODEL + col] =
                    make_float2(acc[mi][ni][2], acc[mi][ni][3]);
            }
    }
}

// ==================== conversion kernels ====================
__global__ __launch_bounds__(256) void split_kernel(
    const float* __restrict__ in, bf16* __restrict__ hi, bf16* __restrict__ lo, int n2)
{
    int i = blockIdx.x * blockDim.x + threadIdx.x;
    if (i >= n2) return;
    float2 v = ((const float2*)in)[i];
    bf16 h0 = __float2bfloat16(v.x);
    bf16 l0 = __float2bfloat16(v.x - __bfloat162float(h0));
    bf16 h1 = __float2bfloat16(v.y);
    bf16 l1 = __float2bfloat16(v.y - __bfloat162float(h1));
    ((uint32_t*)hi)[i] = bf2(h0, h1);
    ((uint32_t*)lo)[i] = bf2(l0, l1);
}

__global__ __launch_bounds__(256) void wT_split3(
    const float* __restrict__ W0, const float* __restrict__ W1,
    const float* __restrict__ W2, bf16* __restrict__ Th, bf16* __restrict__ Tl)
{
    const float* W = (blockIdx.z == 0) ? W0 : (blockIdx.z == 1) ? W1 : W2;
    Th += (size_t)blockIdx.z * WSZ;
    Tl += (size_t)blockIdx.z * WSZ;
    __shared__ float t[32][33];
    int nx = blockIdx.x * 32 + threadIdx.x;
#pragma unroll
    for (int j = 0; j < 32; j += 8)
        t[threadIdx.y + j][threadIdx.x] =
            W[(size_t)(blockIdx.y * 32 + threadIdx.y + j) * D_MODEL + nx];
    __syncthreads();
    int k = blockIdx.y * 32 + threadIdx.x;
#pragma unroll
    for (int j = 0; j < 32; j += 8) {
        int n = blockIdx.x * 32 + threadIdx.y + j;
        float v = t[threadIdx.x][threadIdx.y + j];
        bf16 h = __float2bfloat16(v);
        bf16 l = __float2bfloat16(v - __bfloat162float(h));
        Th[(size_t)n * D_MODEL + k] = h;
        Tl[(size_t)n * D_MODEL + k] = l;
    }
}

// ==================== tensor-core flash attention ====================
// CTA: 128 queries x one (b,h). 8 warps x 16 rows, full kv width 128/warp.
// S = (Qh+Ql)(Kh+Kl)^T 3-term; softmax fp32 in regs; P split hi/lo in regs,
// PV 3-term with V hi/lo via ldmatrix.trans. Double-buffered K/V smem.
#define AROW 144 /* bytes per 64-col bf16 row (128B data + 16B pad) */
#define ATILE (128 * AROW)             /* 18432 */
#define A_SQH 0
#define A_SQL ATILE
#define A_STG (2 * ATILE)              /* stage base 36864 */
#define A_STGSZ (4 * ATILE)            /* 73728 */
#define ATTN_SMEM (2 * ATILE + 2 * A_STGSZ) /* 184320 */

__global__ __launch_bounds__(256, 1) void attn_mma(
    const bf16* __restrict__ Qh, const bf16* __restrict__ Ql,
    const bf16* __restrict__ Kh, const bf16* __restrict__ Kl,
    const bf16* __restrict__ Vh, const bf16* __restrict__ Vl,
    bf16* __restrict__ MH, bf16* __restrict__ ML)
{
    extern __shared__ char smraw[];
    const uint32_t sb = smem_u32(smraw);
    const int tid = threadIdx.x;
    const int wid = tid >> 5, lane = tid & 31;
    const uint32_t lrow = lane & 15, lcol = lane >> 4;
    const int g = lane >> 2, t4 = lane & 3;

    const int q0 = blockIdx.x * 128;
    const int h = blockIdx.y;
    const int b = blockIdx.z;
    const size_t qrow = (size_t)b * SEQ + q0;
    const int hofs = h * HEAD_DIM;

    // ---- load Q tiles (hi/lo) ----
#pragma unroll
    for (int i = 0; i < 8; i++) {
        int f = i * 256 + tid;          // 0..2047
        int arr = f >> 10;              // 0..1
        int r = (f >> 3) & 127, cg = f & 7;
        const bf16* srcp = arr ? Ql : Qh;
        cp16(sb + arr * ATILE + r * AROW + cg * 16,
             srcp + (qrow + r) * D_MODEL + hofs + cg * 8);
    }
    cp_commit();

    const bf16* gsrc[4] = {Kh, Kl, Vh, Vl};
    auto load_kv = [&](int t, int s) {
        const uint32_t st = sb + A_STG + s * A_STGSZ;
        const size_t krow = (size_t)b * SEQ + t * 128;
#pragma unroll
        for (int i = 0; i < 16; i++) {
            int f = i * 256 + tid;      // 0..4095
            int arr = f >> 10;
            int r = (f >> 3) & 127, cg = f & 7;
            cp16(st + arr * ATILE + r * AROW + cg * 16,
                 gsrc[arr] + (krow + r) * D_MODEL + hofs + cg * 8);
        }
    };

    load_kv(0, 0);
    cp_commit();
    cp_wait<1>();   // Q done
    __syncthreads();

    // preload Q fragments (A operand), all 4 k-chunks, hi & lo
    uint32_t qhf[4][4], qlf[4][4];
#pragma unroll
    for (int kc = 0; kc < 4; kc++) {
        ldsm4(qhf[kc], sb + A_SQH + (wid * 16 + lrow) * AROW + kc * 32 + lcol * 16);
        ldsm4(qlf[kc], sb + A_SQL + (wid * 16 + lrow) * AROW + kc * 32 + lcol * 16);
    }

    float o[8][4];
#pragma unroll
    for (int di = 0; di < 8; di++)
#pragma unroll
        for (int j = 0; j < 4; j++) o[di][j] = 0.f;
    float m_prev[2] = {-1e30f, -1e30f};
    float lsum[2] = {0.f, 0.f};

    const int NT = SEQ / 128;  // 16
    for (int t = 0; t < NT; t++) {
        if (t + 1 < NT) {
            load_kv(t + 1, (t + 1) & 1);
            cp_commit();
            cp_wait<1>();
        } else {
            cp_wait<0>();
        }
        __syncthreads();

        const uint32_t st = sb + A_STG + (t & 1) * A_STGSZ;
        const uint32_t skh = st, skl = st + ATILE;
        const uint32_t svh = st + 2 * ATILE, svl = st + 3 * ATILE;

        // ---- S = Q K^T (3-term) ----
        float s[16][4];
#pragma unroll
        for (int ni = 0; ni < 16; ni++)
#pragma unroll
            for (int j = 0; j < 4; j++) s[ni][j] = 0.f;

#pragma unroll
        for (int kc = 0; kc < 4; kc++) {
            uint32_t kf[8][4];
#pragma unroll
            for (int np = 0; np < 8; np++)
                ldsm4(kf[np], skh + (np * 16 + lrow) * AROW + kc * 32 + lcol * 16);
#pragma unroll
            for (int ni = 0; ni < 16; ni++) {
                int np = ni >> 1, hl = ni & 1;
                mma16816(s[ni], qhf[kc], kf[np][hl], kf[np][hl + 2]);
                mma16816(s[ni], qlf[kc], kf[np][hl], kf[np][hl + 2]);
            }
        }
#pragma unroll
        for (int kc = 0; kc < 4; kc++) {
            uint32_t kf[8][4];
#pragma unroll
            for (int np = 0; np < 8; np++)
                ldsm4(kf[np], skl + (np * 16 + lrow) * AROW + kc * 32 + lcol * 16);
#pragma unroll
            for (int ni = 0; ni < 16; ni++) {
                int np = ni >> 1, hl = ni & 1;
                mma16816(s[ni], qhf[kc], kf[np][hl], kf[np][hl + 2]);
            }
        }

        // ---- online softmax (warp-local; rows split over 4 lanes) ----
#pragma unroll
        for (int rg = 0; rg < 2; rg++) {
            float mx = -1e30f;
#pragma unroll
            for (int ni = 0; ni < 16; ni++)
                mx = fmaxf(mx, fmaxf(s[ni][2 * rg], s[ni][2 * rg + 1]));
            mx = fmaxf(mx, __shfl_xor_sync(0xffffffffu, mx, 1));
            mx = fmaxf(mx, __shfl_xor_sync(0xffffffffu, mx, 2));
            float mn = fmaxf(m_prev[rg], mx);
            float al = __expf(m_prev[rg] - mn);
            float sum = 0.f;
#pragma unroll
            for (int ni = 0; ni < 16; ni++) {
                float p0 = __expf(s[ni][2 * rg] - mn);
                float p1 = __expf(s[ni][2 * rg + 1] - mn);
                s[ni][2 * rg] = p0;
                s[ni][2 * rg + 1] = p1;
                sum += p0 + p1;
            }
            sum += __shfl_xor_sync(0xffffffffu, sum, 1);
            sum += __shfl_xor_sync(0xffffffffu, sum, 2);
            lsum[rg] = lsum[rg] * al + sum;
            m_prev[rg] = mn;
#pragma unroll
            for (int di = 0; di < 8; di++) {
                o[di][2 * rg] *= al;
                o[di][2 * rg + 1] *= al;
            }
        }

        // ---- O += P V (3-term, P from regs, V via ldmatrix.trans) ----
#pragma unroll
        for (int kc2 = 0; kc2 < 8; kc2++) {
            int j0 = 2 * kc2, j1 = j0 + 1;
            uint32_t ah[4], al4[4];
#pragma unroll
            for (int q = 0; q < 4; q++) {
                const float* sp = (q & 2) ? s[j1] : s[j0];
                float v0 = sp[(q & 1) * 2], v1 = sp[(q & 1) * 2 + 1];
                bf16 h0 = __float2bfloat16(v0);
                bf16 h1 = __float2bfloat16(v1);
                ah[q] = bf2(h0, h1);
                al4[q] = bf2(__float2bfloat16(v0 - __bfloat162float(h0)),
                             __float2bfloat16(v1 - __bfloat162float(h1)));
            }
            uint32_t vhf[4][4], vlf[4][4];
#pragma unroll
            for (int dp = 0; dp < 4; dp++) {
                uint32_t a = (kc2 * 16 + lrow) * AROW + (dp * 16 + lcol * 8) * 2;
                ldsm4t(vhf[dp], svh + a);
                ldsm4t(vlf[dp], svl + a);
            }
#pragma unroll
            for (int di = 0; di < 8; di++) {
                int dp = di >> 1, off = (di & 1) * 2;
                mma16816(o[di], ah, vhf[dp][off], vhf[dp][off + 1]);
                mma16816(o[di], ah, vlf[dp][off], vlf[dp][off + 1]);
                mma16816(o[di], al4, vhf[dp][off], vhf[dp][off + 1]);
            }
        }
        __syncthreads();
    }

    // ---- epilogue: normalize, split hi/lo, store merged ----
    float inv_l[2] = {1.f / lsum[0], 1.f / lsum[1]};
#pragma unroll
    for (int di = 0; di < 8; di++) {
#pragma unroll
        for (int rg = 0; rg < 2; rg++) {
            float v0 = o[di][2 * rg] * inv_l[rg];
            float v1 = o[di][2 * rg + 1] * inv_l[rg];
            bf16 h0 = __float2bfloat16(v0);
            bf16 h1 = __float2bfloat16(v1);
            size_t idx = (qrow + wid * 16 + g + 8 * rg) * D_MODEL + hofs + di * 8 + t4 * 2;
            *(uint32_t*)&MH[idx] = bf2(h0, h1);
            *(uint32_t*)&ML[idx] = bf2(__float2bfloat16(v0 - __bfloat162float(h0)),
                                       __float2bfloat16(v1 - __bfloat162float(h1)));
        }
    }
}

// ---------------------------------------------------------------------------
extern "C" void kernel_launch(void* const* d_in, const int* in_sizes, int n_in,
                              void* d_out, int out_size)
{
    (void)in_sizes; (void)n_in; (void)out_size;
    const float* x    = (const float*)d_in[0];
    const float* W_q  = (const float*)d_in[1];
    const float* W_k  = (const float*)d_in[2];
    const float* W_v  = (const float*)d_in[3];
    const float* fc_o = (const float*)d_in[4];
    float* out = (float*)d_out;

    bf16 *xh, *xl, *qkvh, *qkvl, *mh, *ml, *wh, *wl;
    cudaGetSymbolAddress((void**)&xh, g_xh);
    cudaGetSymbolAddress((void**)&xl, g_xl);
    cudaGetSymbolAddress((void**)&qkvh, g_qkvh);
    cudaGetSymbolAddress((void**)&qkvl, g_qkvl);
    cudaGetSymbolAddress((void**)&mh, g_mh);
    cudaGetSymbolAddress((void**)&ml, g_ml);
    cudaGetSymbolAddress((void**)&wh, g_wh);
    cudaGetSymbolAddress((void**)&wl, g_wl);

    cudaFuncSetAttribute(gemm_mma, cudaFuncAttributeMaxDynamicSharedMemorySize, GEMM_SMEM);
    cudaFuncSetAttribute(attn_mma, cudaFuncAttributeMaxDynamicSharedMemorySize, ATTN_SMEM);

    const int n2_x = MTOT * D_MODEL / 2;
    dim3 wgrid(D_MODEL / 32, D_MODEL / 32, 3);
    dim3 wblk(32, 8);

    split_kernel<<<(n2_x + 255) / 256, 256>>>(x, xh, xl, n2_x);
    wT_split3<<<wgrid, wblk>>>(W_q, W_k, W_v, wh, wl);

    // QKV: split bf16 outputs, Q pre-scaled by 1/sqrt(Hd)
    dim3 ggrid3(D_MODEL / 128, MTOT / 128, 3);
    gemm_mma<<<ggrid3, 256, GEMM_SMEM>>>(xh, xl, wh, wl, nullptr, qkvh, qkvl, 0.125f);

    // attention (tensor core) -> merged bf16 hi/lo
    const size_t PL = (size_t)MTOT * D_MODEL;
    dim3 attn_grid(SEQ / 128, HEADS, BATCH);  // (16,16,4)
    attn_mma<<<attn_grid, 256, ATTN_SMEM>>>(qkvh, qkvl, qkvh + PL, qkvl + PL,
                                            qkvh + 2 * PL, qkvl + 2 * PL, mh, ml);

    // out-proj: fp32 output
    dim3 wgrid1(D_MODEL / 32, D_MODEL / 32, 1);
    wT_split3<<<wgrid1, wblk>>>(fc_o, fc_o, fc_o, wh, wl);
    dim3 ggrid1(D_MODEL / 128, MTOT / 128, 1);
    gemm_mma<<<ggrid1, 256, GEMM_SMEM>>>(mh, ml, wh, wl, out, nullptr, nullptr, 1.0f);
}

// round 6
// speedup vs baseline: 1.0063x; 1.0063x over previous
#include <cuda_runtime.h>
#include <cuda_bf16.h>
#include <math.h>
#include <stdint.h>

#define D_MODEL 1024
#define HEADS 16
#define HEAD_DIM 64
#define BATCH 4
#define SEQ 2048
#define MTOT (BATCH * SEQ) /* 8192 */
#define WSZ (D_MODEL * D_MODEL)

typedef __nv_bfloat16 bf16;

// ---- scratch (static __device__; allocation APIs forbidden) ----
__device__ bf16 g_xh[(size_t)MTOT * D_MODEL];
__device__ bf16 g_xl[(size_t)MTOT * D_MODEL];
__device__ bf16 g_qkvh[(size_t)3 * MTOT * D_MODEL];
__device__ bf16 g_qkvl[(size_t)3 * MTOT * D_MODEL];
__device__ bf16 g_mh[(size_t)MTOT * D_MODEL];
__device__ bf16 g_ml[(size_t)MTOT * D_MODEL];
__device__ bf16 g_wh[(size_t)3 * WSZ];
__device__ bf16 g_wl[(size_t)3 * WSZ];

// ============================ PTX helpers ============================
__device__ __forceinline__ uint32_t smem_u32(const void* p) {
    uint32_t a;
    asm("{ .reg .u64 t; cvta.to.shared.u64 t, %1; cvt.u32.u64 %0, t; }"
        : "=r"(a) : "l"(p));
    return a;
}
__device__ __forceinline__ void cp16(uint32_t s, const void* g) {
    asm volatile("cp.async.cg.shared.global [%0], [%1], 16;" :: "r"(s), "l"(g) : "memory");
}
__device__ __forceinline__ void cp_commit() {
    asm volatile("cp.async.commit_group;" ::: "memory");
}
template <int N> __device__ __forceinline__ void cp_wait() {
    asm volatile("cp.async.wait_group %0;" :: "n"(N) : "memory");
}
__device__ __forceinline__ void ldsm4(uint32_t* r, uint32_t addr) {
    asm volatile("ldmatrix.sync.aligned.m8n8.x4.shared.b16 {%0,%1,%2,%3}, [%4];"
                 : "=r"(r[0]), "=r"(r[1]), "=r"(r[2]), "=r"(r[3]) : "r"(addr));
}
__device__ __forceinline__ void ldsm4t(uint32_t* r, uint32_t addr) {
    asm volatile("ldmatrix.sync.aligned.m8n8.x4.trans.shared.b16 {%0,%1,%2,%3}, [%4];"
                 : "=r"(r[0]), "=r"(r[1]), "=r"(r[2]), "=r"(r[3]) : "r"(addr));
}
__device__ __forceinline__ void mma16816(float* c, const uint32_t* a,
                                         uint32_t b0, uint32_t b1) {
    asm volatile(
        "mma.sync.aligned.m16n8k16.row.col.f32.bf16.bf16.f32 "
        "{%0,%1,%2,%3},{%4,%5,%6,%7},{%8,%9},{%0,%1,%2,%3};"
        : "+f"(c[0]), "+f"(c[1]), "+f"(c[2]), "+f"(c[3])
        : "r"(a[0]), "r"(a[1]), "r"(a[2]), "r"(a[3]), "r"(b0), "r"(b1));
}
__device__ __forceinline__ uint32_t bf2(bf16 a, bf16 b) {
    __nv_bfloat162 t; t.x = a; t.y = b;
    return *(uint32_t*)&t;
}

// ============================ mma.sync GEMM ============================
// C = A @ W, 3-term bf16 split. 128x128 tile, BK=32, 8 warps (4x2),
// 2-stage cp.async. Fragment-reuse inner loop: 12 LDSM / k16.
#define BK 32
#define NCHUNK (D_MODEL / BK) /* 32 */
#define ROW_B 80
#define TILE_B (128 * ROW_B)
#define STAGE_B (4 * TILE_B)
#define GEMM_SMEM (2 * STAGE_B) /* 81920 */

__global__ __launch_bounds__(256, 2) void gemm_mma(
    const bf16* __restrict__ Ah, const bf16* __restrict__ Al,
    const bf16* __restrict__ BhAll, const bf16* __restrict__ BlAll,
    float* __restrict__ Cf, bf16* __restrict__ ChAll, bf16* __restrict__ ClAll,
    float scale0)
{
    extern __shared__ char smem[];
    const uint32_t sb = smem_u32(smem);
    const int tid = threadIdx.x;
    const int wid = tid >> 5, lane = tid & 31;
    const int wm = wid & 3, wn = wid >> 2;
    const int rowBase = blockIdx.y * 128;
    const int colBase = blockIdx.x * 128;

    const bf16* Bh = BhAll + (size_t)blockIdx.z * WSZ;
    const bf16* Bl = BlAll + (size_t)blockIdx.z * WSZ;

    const bf16* src[4] = {
        Ah + (size_t)rowBase * D_MODEL, Al + (size_t)rowBase * D_MODEL,
        Bh + (size_t)colBase * D_MODEL, Bl + (size_t)colBase * D_MODEL};

    float acc[2][8][4];
#pragma unroll
    for (int mi = 0; mi < 2; mi++)
#pragma unroll
        for (int ni = 0; ni < 8; ni++)
#pragma unroll
            for (int j = 0; j < 4; j++) acc[mi][ni][j] = 0.f;

    auto load_chunk = [&](int c, int s) {
        const uint32_t tb = sb + s * STAGE_B;
        const int kofs = c * BK;
#pragma unroll
        for (int t = 0; t < 4; t++) {
#pragma unroll
            for (int i = 0; i < 2; i++) {
                int f = i * 256 + tid;
                int row = f >> 2, cc = f & 3;
                cp16(tb + t * TILE_B + row * ROW_B + cc * 16,
                     src[t] + (size_t)row * D_MODEL + kofs + cc * 8);
            }
        }
    };

    const uint32_t lrow = lane & 15, lcol = lane >> 4;

    load_chunk(0, 0);
    cp_commit();

    for (int c = 0; c < NCHUNK; c++) {
        if (c + 1 < NCHUNK) {
            load_chunk(c + 1, (c + 1) & 1);
            cp_commit();
            cp_wait<1>();
        } else {
            cp_wait<0>();
        }
        __syncthreads();

        const uint32_t tb = sb + (c & 1) * STAGE_B;
        const uint32_t aTh = tb, aTl = tb + TILE_B;
        const uint32_t bTh = tb + 2 * TILE_B, bTl = tb + 3 * TILE_B;

#pragma unroll
        for (int k16 = 0; k16 < 2; k16++) {
            const uint32_t kb = k16 * 32;
            const uint32_t arow = (wm * 32 + lrow) * ROW_B + kb + lcol * 16;
            uint32_t a_h[2][4], a_l[2][4];
            ldsm4(a_h[0], aTh + arow);
            ldsm4(a_h[1], aTh + arow + 16 * ROW_B);
            ldsm4(a_l[0], aTl + arow);
            ldsm4(a_l[1], aTl + arow + 16 * ROW_B);
            // pass 1+2: Bh against Ah and Al
#pragma unroll
            for (int nb = 0; nb < 4; nb++) {
                uint32_t bh[4];
                ldsm4(bh, bTh + (wn * 64 + nb * 16 + lrow) * ROW_B + kb + lcol * 16);
#pragma unroll
                for (int mi = 0; mi < 2; mi++) {
                    mma16816(acc[mi][2 * nb], a_h[mi], bh[0], bh[2]);
                    mma16816(acc[mi][2 * nb + 1], a_h[mi], bh[1], bh[3]);
                    mma16816(acc[mi][2 * nb], a_l[mi], bh[0], bh[2]);
                    mma16816(acc[mi][2 * nb + 1], a_l[mi], bh[1], bh[3]);
                }
            }
            // pass 3: Bl against Ah
#pragma unroll
            for (int nb = 0; nb < 4; nb++) {
                uint32_t bl[4];
                ldsm4(bl, bTl + (wn * 64 + nb * 16 + lrow) * ROW_B + kb + lcol * 16);
#pragma unroll
                for (int mi = 0; mi < 2; mi++) {
                    mma16816(acc[mi][2 * nb], a_h[mi], bl[0], bl[2]);
                    mma16816(acc[mi][2 * nb + 1], a_h[mi], bl[1], bl[3]);
                }
            }
        }
        __syncthreads();
    }

    // Epilogue
    const int g = lane >> 2, t4 = lane & 3;
    if (ChAll) {
        bf16* Ch = ChAll + (size_t)blockIdx.z * MTOT * D_MODEL;
        bf16* Cl = ClAll + (size_t)blockIdx.z * MTOT * D_MODEL;
        const float sc = (blockIdx.z == 0) ? scale0 : 1.0f;
#pragma unroll
        for (int mi = 0; mi < 2; mi++)
#pragma unroll
            for (int ni = 0; ni < 8; ni++) {
                int r = rowBase + wm * 32 + mi * 16 + g;
                int col = colBase + wn * 64 + ni * 8 + t4 * 2;
#pragma unroll
                for (int half = 0; half < 2; half++) {
                    float v0 = acc[mi][ni][2 * half] * sc;
                    float v1 = acc[mi][ni][2 * half + 1] * sc;
                    bf16 h0 = __float2bfloat16(v0);
                    bf16 h1 = __float2bfloat16(v1);
                    bf16 l0 = __float2bfloat16(v0 - __bfloat162float(h0));
                    bf16 l1 = __float2bfloat16(v1 - __bfloat162float(h1));
                    size_t o = (size_t)(r + 8 * half) * D_MODEL + col;
                    *(uint32_t*)&Ch[o] = bf2(h0, h1);
                    *(uint32_t*)&Cl[o] = bf2(l0, l1);
                }
            }
    } else {
#pragma unroll
        for (int mi = 0; mi < 2; mi++)
#pragma unroll
            for (int ni = 0; ni < 8; ni++) {
                int r = rowBase + wm * 32 + mi * 16 + g;
                int col = colBase + wn * 64 + ni * 8 + t4 * 2;
                *(float2*)&Cf[(size_t)r * D_MODEL + col] =
                    make_float2(acc[mi][ni][0], acc[mi][ni][1]);
                *(float2*)&Cf[(size_t)(r + 8) * D_MODEL + col] =
                    make_float2(acc[mi][ni][2], acc[mi][ni][3]);
            }
    }
}

// ==================== conversion kernels ====================
__global__ __launch_bounds__(256) void split_kernel(
    const float* __restrict__ in, bf16* __restrict__ hi, bf16* __restrict__ lo, int n2)
{
    int i = blockIdx.x * blockDim.x + threadIdx.x;
    if (i >= n2) return;
    float2 v = ((const float2*)in)[i];
    bf16 h0 = __float2bfloat16(v.x);
    bf16 l0 = __float2bfloat16(v.x - __bfloat162float(h0));
    bf16 h1 = __float2bfloat16(v.y);
    bf16 l1 = __float2bfloat16(v.y - __bfloat162float(h1));
    ((uint32_t*)hi)[i] = bf2(h0, h1);
    ((uint32_t*)lo)[i] = bf2(l0, l1);
}

__global__ __launch_bounds__(256) void wT_split3(
    const float* __restrict__ W0, const float* __restrict__ W1,
    const float* __restrict__ W2, bf16* __restrict__ Th, bf16* __restrict__ Tl)
{
    const float* W = (blockIdx.z == 0) ? W0 : (blockIdx.z == 1) ? W1 : W2;
    Th += (size_t)blockIdx.z * WSZ;
    Tl += (size_t)blockIdx.z * WSZ;
    __shared__ float t[32][33];
    int nx = blockIdx.x * 32 + threadIdx.x;
#pragma unroll
    for (int j = 0; j < 32; j += 8)
        t[threadIdx.y + j][threadIdx.x] =
            W[(size_t)(blockIdx.y * 32 + threadIdx.y + j) * D_MODEL + nx];
    __syncthreads();
    int k = blockIdx.y * 32 + threadIdx.x;
#pragma unroll
    for (int j = 0; j < 32; j += 8) {
        int n = blockIdx.x * 32 + threadIdx.y + j;
        float v = t[threadIdx.x][threadIdx.y + j];
        bf16 h = __float2bfloat16(v);
        bf16 l = __float2bfloat16(v - __bfloat162float(h));
        Th[(size_t)n * D_MODEL + k] = h;
        Tl[(size_t)n * D_MODEL + k] = l;
    }
}

// ==================== tensor-core flash attention v2 ====================
// CTA: 128 threads (4 warps), 64 queries, one (b,h). 2 CTAs/SM.
// Single KV stage; K/V loads phase-pipelined (K loads during softmax+PV,
// V loads during next QK). Q fragments loaded directly from gmem.
#define KROW 144
#define KTILE (128 * KROW)          /* 18432 */
#define ATTN_SMEM (4 * KTILE)       /* 73728: Kh,Kl,Vh,Vl */

__global__ __launch_bounds__(128, 2) void attn_mma(
    const bf16* __restrict__ Qh, const bf16* __restrict__ Ql,
    const bf16* __restrict__ Kh, const bf16* __restrict__ Kl,
    const bf16* __restrict__ Vh, const bf16* __restrict__ Vl,
    bf16* __restrict__ MH, bf16* __restrict__ ML)
{
    extern __shared__ char smraw[];
    const uint32_t sb = smem_u32(smraw);
    const int tid = threadIdx.x;
    const int wid = tid >> 5, lane = tid & 31;
    const uint32_t lrow = lane & 15, lcol = lane >> 4;
    const int g = lane >> 2, t4 = lane & 3;

    const int q0 = blockIdx.x * 64;
    const int h = blockIdx.y;
    const int b = blockIdx.z;
    const size_t qrow = (size_t)b * SEQ + q0;
    const size_t krow0 = (size_t)b * SEQ;
    const int hofs = h * HEAD_DIM;

    const uint32_t skh = sb, skl = sb + KTILE;
    const uint32_t svh = sb + 2 * KTILE, svl = sb + 3 * KTILE;

    auto load_k = [&](int t) {
        const size_t kr = krow0 + (size_t)t * 128;
#pragma unroll
        for (int i = 0; i < 16; i++) {
            int f = i * 128 + tid;       // 0..2047
            int arr = f >> 10;           // 0: Kh, 1: Kl
            int r = (f >> 3) & 127, cg = f & 7;
            const bf16* p = arr ? Kl : Kh;
            cp16(sb + arr * KTILE + r * KROW + cg * 16,
                 p + (kr + r) * D_MODEL + hofs + cg * 8);
        }
    };
    auto load_v = [&](int t) {
        const size_t kr = krow0 + (size_t)t * 128;
#pragma unroll
        for (int i = 0; i < 16; i++) {
            int f = i * 128 + tid;
            int arr = f >> 10;           // 0: Vh, 1: Vl
            int r = (f >> 3) & 127, cg = f & 7;
            const bf16* p = arr ? Vl : Vh;
            cp16(sb + (2 + arr) * KTILE + r * KROW + cg * 16,
                 p + (kr + r) * D_MODEL + hofs + cg * 8);
        }
    };

    load_k(0); cp_commit();
    load_v(0); cp_commit();

    // ---- Q fragments direct from gmem (A-operand layout) ----
    uint32_t qhf[4][4], qlf[4][4];
    {
        const size_t r0 = qrow + wid * 16 + g;
        const int c0 = hofs + t4 * 2;
#pragma unroll
        for (int kc = 0; kc < 4; kc++) {
#pragma unroll
            for (int q = 0; q < 4; q++) {
                size_t r = r0 + ((q & 1) ? 8 : 0);
                int c = c0 + kc * 16 + ((q & 2) ? 8 : 0);
                qhf[kc][q] = *(const uint32_t*)&Qh[r * D_MODEL + c];
                qlf[kc][q] = *(const uint32_t*)&Ql[r * D_MODEL + c];
            }
        }
    }

    float o[8][4];
#pragma unroll
    for (int di = 0; di < 8; di++)
#pragma unroll
        for (int j = 0; j < 4; j++) o[di][j] = 0.f;
    float m_prev[2] = {-1e30f, -1e30f};
    float lsum[2] = {0.f, 0.f};

    const int NT = SEQ / 128;  // 16
    for (int t = 0; t < NT; t++) {
        cp_wait<1>();       // K_t landed (V_t may be pending)
        __syncthreads();

        // ---- S = Q K^T (3-term) ----
        float s[16][4];
#pragma unroll
        for (int ni = 0; ni < 16; ni++)
#pragma unroll
            for (int j = 0; j < 4; j++) s[ni][j] = 0.f;

#pragma unroll
        for (int kc = 0; kc < 4; kc++) {
            uint32_t kf[8][4];
#pragma unroll
            for (int np = 0; np < 8; np++)
                ldsm4(kf[np], skh + (np * 16 + lrow) * KROW + kc * 32 + lcol * 16);
#pragma unroll
            for (int ni = 0; ni < 16; ni++) {
                int np = ni >> 1, hl = ni & 1;
                mma16816(s[ni], qhf[kc], kf[np][hl], kf[np][hl + 2]);
                mma16816(s[ni], qlf[kc], kf[np][hl], kf[np][hl + 2]);
            }
        }
#pragma unroll
        for (int kc = 0; kc < 4; kc++) {
            uint32_t kf[8][4];
#pragma unroll
            for (int np = 0; np < 8; np++)
                ldsm4(kf[np], skl + (np * 16 + lrow) * KROW + kc * 32 + lcol * 16);
#pragma unroll
            for (int ni = 0; ni < 16; ni++) {
                int np = ni >> 1, hl = ni & 1;
                mma16816(s[ni], qhf[kc], kf[np][hl], kf[np][hl + 2]);
            }
        }
        __syncthreads();                 // all warps done reading K_t
        if (t + 1 < NT) { load_k(t + 1); cp_commit(); }

        // ---- online softmax (regs; overlaps K_{t+1} load) ----
#pragma unroll
        for (int rg = 0; rg < 2; rg++) {
            float mx = -1e30f;
#pragma unroll
            for (int ni = 0; ni < 16; ni++)
                mx = fmaxf(mx, fmaxf(s[ni][2 * rg], s[ni][2 * rg + 1]));
            mx = fmaxf(mx, __shfl_xor_sync(0xffffffffu, mx, 1));
            mx = fmaxf(mx, __shfl_xor_sync(0xffffffffu, mx, 2));
            float mn = fmaxf(m_prev[rg], mx);
            float al = __expf(m_prev[rg] - mn);
            float sum = 0.f;
#pragma unroll
            for (int ni = 0; ni < 16; ni++) {
                float p0 = __expf(s[ni][2 * rg] - mn);
                float p1 = __expf(s[ni][2 * rg + 1] - mn);
                s[ni][2 * rg] = p0;
                s[ni][2 * rg + 1] = p1;
                sum += p0 + p1;
            }
            sum += __shfl_xor_sync(0xffffffffu, sum, 1);
            sum += __shfl_xor_sync(0xffffffffu, sum, 2);
            lsum[rg] = lsum[rg] * al + sum;
            m_prev[rg] = mn;
#pragma unroll
            for (int di = 0; di < 8; di++) {
                o[di][2 * rg] *= al;
                o[di][2 * rg + 1] *= al;
            }
        }

        cp_wait<1>();       // V_t landed (K_{t+1} may be pending)
        __syncthreads();

        // ---- O += P V (3-term) ----
#pragma unroll
        for (int kc2 = 0; kc2 < 8; kc2++) {
            int j0 = 2 * kc2, j1 = j0 + 1;
            uint32_t ah[4], al4[4];
#pragma unroll
            for (int q = 0; q < 4; q++) {
                const float* sp = (q & 2) ? s[j1] : s[j0];
                float v0 = sp[(q & 1) * 2], v1 = sp[(q & 1) * 2 + 1];
                bf16 h0 = __float2bfloat16(v0);
                bf16 h1 = __float2bfloat16(v1);
                ah[q] = bf2(h0, h1);
                al4[q] = bf2(__float2bfloat16(v0 - __bfloat162float(h0)),
                             __float2bfloat16(v1 - __bfloat162float(h1)));
            }
            uint32_t vhf[4][4], vlf[4][4];
#pragma unroll
            for (int dp = 0; dp < 4; dp++) {
                uint32_t a = (kc2 * 16 + lrow) * KROW + (dp * 16 + lcol * 8) * 2;
                ldsm4t(vhf[dp], svh + a);
                ldsm4t(vlf[dp], svl + a);
            }
#pragma unroll
            for (int di = 0; di < 8; di++) {
                int dp = di >> 1, off = (di & 1) * 2;
                mma16816(o[di], ah, vhf[dp][off], vhf[dp][off + 1]);
                mma16816(o[di], ah, vlf[dp][off], vlf[dp][off + 1]);
                mma16816(o[di], al4, vhf[dp][off], vhf[dp][off + 1]);
            }
        }
        __syncthreads();                 // all warps done reading V_t
        if (t + 1 < NT) { load_v(t + 1); cp_commit(); }
    }

    // ---- epilogue: normalize, split hi/lo, store merged ----
    float inv_l[2] = {1.f / lsum[0], 1.f / lsum[1]};
#pragma unroll
    for (int di = 0; di < 8; di++) {
#pragma unroll
        for (int rg = 0; rg < 2; rg++) {
            float v0 = o[di][2 * rg] * inv_l[rg];
            float v1 = o[di][2 * rg + 1] * inv_l[rg];
            bf16 h0 = __float2bfloat16(v0);
            bf16 h1 = __float2bfloat16(v1);
            size_t idx = (qrow + wid * 16 + g + 8 * rg) * D_MODEL + hofs + di * 8 + t4 * 2;
            *(uint32_t*)&MH[idx] = bf2(h0, h1);
            *(uint32_t*)&ML[idx] = bf2(__float2bfloat16(v0 - __bfloat162float(h0)),
                                       __float2bfloat16(v1 - __bfloat162float(h1)));
        }
    }
}

// ---------------------------------------------------------------------------
extern "C" void kernel_launch(void* const* d_in, const int* in_sizes, int n_in,
                              void* d_out, int out_size)
{
    (void)in_sizes; (void)n_in; (void)out_size;
    const float* x    = (const float*)d_in[0];
    const float* W_q  = (const float*)d_in[1];
    const float* W_k  = (const float*)d_in[2];
    const float* W_v  = (const float*)d_in[3];
    const float* fc_o = (const float*)d_in[4];
    float* out = (float*)d_out;

    bf16 *xh, *xl, *qkvh, *qkvl, *mh, *ml, *wh, *wl;
    cudaGetSymbolAddress((void**)&xh, g_xh);
    cudaGetSymbolAddress((void**)&xl, g_xl);
    cudaGetSymbolAddress((void**)&qkvh, g_qkvh);
    cudaGetSymbolAddress((void**)&qkvl, g_qkvl);
    cudaGetSymbolAddress((void**)&mh, g_mh);
    cudaGetSymbolAddress((void**)&ml, g_ml);
    cudaGetSymbolAddress((void**)&wh, g_wh);
    cudaGetSymbolAddress((void**)&wl, g_wl);

    cudaFuncSetAttribute(gemm_mma, cudaFuncAttributeMaxDynamicSharedMemorySize, GEMM_SMEM);
    cudaFuncSetAttribute(attn_mma, cudaFuncAttributeMaxDynamicSharedMemorySize, ATTN_SMEM);

    const int n2_x = MTOT * D_MODEL / 2;
    dim3 wgrid(D_MODEL / 32, D_MODEL / 32, 3);
    dim3 wblk(32, 8);

    split_kernel<<<(n2_x + 255) / 256, 256>>>(x, xh, xl, n2_x);
    wT_split3<<<wgrid, wblk>>>(W_q, W_k, W_v, wh, wl);

    // QKV: split bf16 outputs, Q pre-scaled by 1/sqrt(Hd)
    dim3 ggrid3(D_MODEL / 128, MTOT / 128, 3);
    gemm_mma<<<ggrid3, 256, GEMM_SMEM>>>(xh, xl, wh, wl, nullptr, qkvh, qkvl, 0.125f);

    // attention (tensor core, 2 CTAs/SM) -> merged bf16 hi/lo
    const size_t PL = (size_t)MTOT * D_MODEL;
    dim3 attn_grid(SEQ / 64, HEADS, BATCH);  // (32,16,4)
    attn_mma<<<attn_grid, 128, ATTN_SMEM>>>(qkvh, qkvl, qkvh + PL, qkvl + PL,
                                            qkvh + 2 * PL, qkvl + 2 * PL, mh, ml);

    // out-proj: fp32 output
    dim3 wgrid1(D_MODEL / 32, D_MODEL / 32, 1);
    wT_split3<<<wgrid1, wblk>>>(fc_o, fc_o, fc_o, wh, wl);
    dim3 ggrid1(D_MODEL / 128, MTOT / 128, 1);
    gemm_mma<<<ggrid1, 256, GEMM_SMEM>>>(mh, ml, wh, wl, out, nullptr, nullptr, 1.0f);
}